// round 1
// baseline (speedup 1.0000x reference)
#include <cuda_runtime.h>
#include <math.h>
#include <stdint.h>

#define BATCH 32
#define MM 5120
#define NC 80
#define TOPK 1000

// ---------------- scratch (device globals: no allocation allowed) -------------
__device__ float g_scores[BATCH * MM];
__device__ int   g_labels[BATCH * MM];

// ---------------- kernel 1: per-anchor score + label -------------------------
// one warp per row of 80 class logits.
__global__ void k1_score(const float* __restrict__ conf,
                         const float* __restrict__ cls) {
    int gw   = (blockIdx.x * blockDim.x + threadIdx.x) >> 5;   // global row
    int lane = threadIdx.x & 31;
    if (gw >= BATCH * MM) return;
    const float* c = cls + (size_t)gw * NC;
    float e0 = c[lane];
    float e1 = c[lane + 32];
    float e2 = (lane < 16) ? c[lane + 64] : -INFINITY;

    // local argmax, first occurrence wins (strict >)
    float m = e0; int mi = lane;
    if (e1 > m) { m = e1; mi = lane + 32; }
    if (e2 > m) { m = e2; mi = lane + 64; }
    // warp reduce (tie -> smaller index, matching jnp.argmax)
    #pragma unroll
    for (int off = 16; off; off >>= 1) {
        float om = __shfl_xor_sync(0xffffffffu, m,  off);
        int   oi = __shfl_xor_sync(0xffffffffu, mi, off);
        if (om > m || (om == m && oi < mi)) { m = om; mi = oi; }
    }
    float s = expf(e0 - m) + expf(e1 - m) + ((lane < 16) ? expf(e2 - m) : 0.0f);
    #pragma unroll
    for (int off = 16; off; off >>= 1)
        s += __shfl_xor_sync(0xffffffffu, s, off);

    if (lane == 0) {
        float cf  = conf[gw];
        float sig = 1.0f / (1.0f + expf(-cf));
        g_scores[gw] = sig / s;     // sigmoid * max(softmax) = sigmoid / sumexp
        g_labels[gw] = mi;
    }
}

// ---------------- kernel 2: per-batch topk + decode + NMS ---------------------
// SMEM layout (bytes):
#define OFF_HIST   0          // u32[32768]  (128KB) -> reused as maskT[32][1024]
#define OFF_DKEYS  131072     // u32[5120]   -> reused as top arrays below
#define OFF_GD     151552     // u32[5120]
#define OFF_GIDX   172032     // u16[5120]
#define OFF_WS     182272     // u32[32]
#define OFF_KW     182400     // u32[2][32]
#define OFF_FLAG   182656     // u32
#define SMEM_BYTES 182784
// top-1000 arrays (valid after selection; overlap dkeys/gd which are dead):
#define OFF_SIDX   131072     // u32[1000]
#define OFF_SSC    135072     // f32[1000]
#define OFF_BX1    139072     // f32[1000]  (offset boxes: clipped + 2*label)
#define OFF_BY1    143072
#define OFF_BX2    147072
#define OFF_BY2    151072
#define OFF_BAREA  155072

__global__ void __launch_bounds__(1024, 1)
k2_topk_nms(const float* __restrict__ reg_pred,
            const float* __restrict__ anchors,
            float* __restrict__ out) {
    extern __shared__ unsigned char smem[];
    unsigned int*   hist   = (unsigned int*)(smem + OFF_HIST);
    unsigned int*   dkeys  = (unsigned int*)(smem + OFF_DKEYS);
    unsigned int*   gd     = (unsigned int*)(smem + OFF_GD);
    unsigned short* gidx   = (unsigned short*)(smem + OFF_GIDX);
    unsigned int*   wsums  = (unsigned int*)(smem + OFF_WS);
    unsigned int*   kwbuf  = (unsigned int*)(smem + OFF_KW);
    unsigned int*   flagp  = (unsigned int*)(smem + OFF_FLAG);
    unsigned int*   sidx   = (unsigned int*)(smem + OFF_SIDX);
    float*          sscore = (float*)(smem + OFF_SSC);
    float*          bx1    = (float*)(smem + OFF_BX1);
    float*          by1    = (float*)(smem + OFF_BY1);
    float*          bx2    = (float*)(smem + OFF_BX2);
    float*          by2    = (float*)(smem + OFF_BY2);
    float*          barea  = (float*)(smem + OFF_BAREA);
    unsigned int*   maskT  = hist;                 // [w*1024 + j]

    const int b    = blockIdx.x;
    const int tid  = threadIdx.x;
    const int warp = tid >> 5;
    const int lane = tid & 31;
    const float* sc = g_scores + (size_t)b * MM;

    // ---- S1: zero histogram ----
    for (int i = tid; i < 32768; i += 1024) hist[i] = 0u;
    __syncthreads();

    // ---- S2: keys + histogram. key d = ~bits(score): ascending d == descending score.
    for (int i = tid; i < MM; i += 1024) {
        unsigned int d = ~__float_as_uint(sc[i]);
        dkeys[i] = d;
        atomicAdd(&hist[d >> 17], 1u);
    }
    __syncthreads();

    // ---- S3: exclusive prefix sum over 32768 bins (32 per thread) ----
    {
        int base = tid * 32;
        unsigned int s = 0;
        #pragma unroll 8
        for (int k = 0; k < 32; k++) s += hist[base + k];
        unsigned int v = s;
        #pragma unroll
        for (int off = 1; off < 32; off <<= 1) {
            unsigned int t = __shfl_up_sync(0xffffffffu, v, off);
            if (lane >= off) v += t;
        }
        if (lane == 31) wsums[warp] = v;
        __syncthreads();
        if (tid < 32) {
            unsigned int w = wsums[tid];
            #pragma unroll
            for (int off = 1; off < 32; off <<= 1) {
                unsigned int t = __shfl_up_sync(0xffffffffu, w, off);
                if (tid >= off) w += t;
            }
            wsums[tid] = w;
        }
        __syncthreads();
        unsigned int run = (v - s) + ((warp > 0) ? wsums[warp - 1] : 0u);
        #pragma unroll 8
        for (int k = 0; k < 32; k++) {
            unsigned int h = hist[base + k];
            hist[base + k] = run;
            run += h;
        }
    }
    __syncthreads();

    // ---- S4: scatter into bin-grouped order (post: hist[b] = cum[b+1]) ----
    for (int i = tid; i < MM; i += 1024) {
        unsigned int d = dkeys[i];
        unsigned int p = atomicAdd(&hist[d >> 17], 1u);
        gd[p]   = d;
        gidx[p] = (unsigned short)i;
    }
    __syncthreads();

    // ---- S5: exact rank within bin -> top-1000 (stable: (score desc, idx asc)) ----
    for (int p = tid; p < MM; p += 1024) {
        unsigned int d   = gd[p];
        unsigned int idx = gidx[p];
        unsigned int bin = d >> 17;
        unsigned int start = hist[bin - 1];   // == orig cum[bin]
        if (start >= TOPK) continue;
        unsigned int end = hist[bin];         // == orig cum[bin+1]
        unsigned int r = start;
        for (unsigned int q = start; q < end; q++) {
            unsigned int dq = gd[q];
            if (dq < d || (dq == d && gidx[q] < idx)) r++;
        }
        if (r < TOPK) { sidx[r] = idx; sscore[r] = __uint_as_float(~d); }
    }
    __syncthreads();

    // ---- S6: decode boxes; write labels/bboxes outputs; keep offset boxes for NMS ----
    for (int k = tid; k < TOPK; k += 1024) {
        unsigned int idx = sidx[k];
        const float* rp = reg_pred + ((size_t)b * MM + idx) * 4;
        float tx = rp[0], ty = rp[1], tw = rp[2], th = rp[3];
        const float* an = anchors + (size_t)idx * 4;
        float ax = an[0], ay = an[1], aw = an[2], ah = an[3];
        float cx = (1.0f / (1.0f + expf(-tx))) * 16.0f + ax;
        float cy = (1.0f / (1.0f + expf(-ty))) * 16.0f + ay;
        float w  = expf(tw) * aw;
        float h  = expf(th) * ah;
        float x1 = fminf(fmaxf((cx - 0.5f * w) * (1.0f / 512.0f), 0.0f), 1.0f);
        float y1 = fminf(fmaxf((cy - 0.5f * h) * (1.0f / 512.0f), 0.0f), 1.0f);
        float x2 = fminf(fmaxf((cx + 0.5f * w) * (1.0f / 512.0f), 0.0f), 1.0f);
        float y2 = fminf(fmaxf((cy + 0.5f * h) * (1.0f / 512.0f), 0.0f), 1.0f);
        float lf  = (float)g_labels[(size_t)b * MM + idx];
        float off = 2.0f * lf;
        float ox1 = x1 + off, oy1 = y1 + off, ox2 = x2 + off, oy2 = y2 + off;
        bx1[k] = ox1; by1[k] = oy1; bx2[k] = ox2; by2[k] = oy2;
        barea[k] = (ox2 - ox1) * (oy2 - oy1);      // areas from offset boxes (ref-exact)
        // outputs: labels + bboxes
        out[32000 + b * TOPK + k] = lf;
        size_t bb = 64000 + ((size_t)b * TOPK + k) * 4;
        out[bb + 0] = x1; out[bb + 1] = y1; out[bb + 2] = x2; out[bb + 3] = y2;
    }
    __syncthreads();

    // ---- S7: suppression mask maskT[w][j]: bit i set iff i<j and iou(i,j)>0.6 ----
    for (int j = warp; j < TOPK; j += 32) {
        float jx1 = bx1[j], jy1 = by1[j], jx2 = bx2[j], jy2 = by2[j], ja = barea[j];
        int tmax = j >> 5;
        for (int t = 0; t <= tmax; t++) {
            int i = t * 32 + lane;
            bool sup = false;
            if (i < j) {
                float xx1 = fmaxf(bx1[i], jx1);
                float yy1 = fmaxf(by1[i], jy1);
                float xx2 = fminf(bx2[i], jx2);
                float yy2 = fminf(by2[i], jy2);
                float w = fmaxf(1e-28f, xx2 - xx1);
                float h = fmaxf(1e-28f, yy2 - yy1);
                float inter = w * h;
                float iou = inter / (barea[i] + ja - inter + 1e-14f);
                sup = iou > 0.6f;
            }
            unsigned int word = __ballot_sync(0xffffffffu, sup);
            if (lane == 0) maskT[t * 1024 + j] = word;
        }
        if (lane > tmax) maskT[lane * 1024 + j] = 0u;
    }
    if (tid < 32) kwbuf[tid] = (tid < 31) ? 0xffffffffu : 0xffu;  // 1000 bits set
    __syncthreads();

    // ---- S8: greedy NMS as Jacobi fixpoint of keep[j] = !exists i<j: keep[i] & sup(i,j)
    int cur = 0;
    for (int it = 0; it < TOPK + 8; it++) {
        unsigned int* kwc = kwbuf + cur * 32;
        unsigned int* kwn = kwbuf + (cur ^ 1) * 32;
        unsigned int supp = 0;
        #pragma unroll
        for (int w = 0; w < 32; w++)
            supp |= maskT[w * 1024 + tid] & kwc[w];
        bool nk = (supp == 0u) && (tid < TOPK);
        unsigned int word = __ballot_sync(0xffffffffu, nk);
        if (lane == 0) kwn[warp] = word;
        __syncthreads();
        if (tid == 0) {
            unsigned int diff = 0;
            #pragma unroll
            for (int w = 0; w < 32; w++) diff |= kwc[w] ^ kwn[w];
            *flagp = diff;
        }
        __syncthreads();
        cur ^= 1;
        if (*flagp == 0u) break;
        __syncthreads();
    }

    // ---- S9: final keep + scores out ----
    if (tid < TOPK) {
        unsigned int kb = (kwbuf[cur * 32 + (tid >> 5)] >> (tid & 31)) & 1u;
        float s = sscore[tid];
        bool keep = kb && (s >= 0.05f);
        out[b * TOPK + tid]          = keep ? s : 0.0f;
        out[192000 + b * TOPK + tid] = keep ? 1.0f : 0.0f;
    }
}

// ---------------- launch ------------------------------------------------------
extern "C" void kernel_launch(void* const* d_in, const int* in_sizes, int n_in,
                              void* d_out, int out_size) {
    const float* conf = (const float*)d_in[0];
    const float* cls  = (const float*)d_in[1];
    const float* reg  = (const float*)d_in[2];
    const float* anc  = (const float*)d_in[3];
    float* out = (float*)d_out;

    cudaFuncSetAttribute(k2_topk_nms,
                         cudaFuncAttributeMaxDynamicSharedMemorySize, SMEM_BYTES);

    // kernel 1: 163840 rows, 8 warps/block
    k1_score<<<(BATCH * MM) / 8, 256>>>(conf, cls);
    // kernel 2: one block per batch
    k2_topk_nms<<<BATCH, 1024, SMEM_BYTES>>>(reg, anc, out);
}